// round 4
// baseline (speedup 1.0000x reference)
#include <cuda_runtime.h>

#define N_NODES 100000
#define N_EDGES 1600000
#define NF 64
#define NH 16
#define E4 (N_EDGES / 4)   // 400000 quad-edge groups

// scratch (no allocs allowed) — 16B-aligned for float4 / red.v4 access
__device__ __align__(16) float g_xl[N_NODES * NH];     // x @ Wl1
__device__ __align__(16) float g_xr[N_NODES * NH];     // x @ Wr1
__device__ __align__(16) float g_agg1[N_NODES * NH];   // segment_sum of xl[src]
__device__ __align__(16) float g_hl[N_NODES];          // h @ Wl2 (scalar per node)
__device__ __align__(16) int2  g_rec[N_EDGES];         // compacted (src, dst-or-neg)

__device__ __forceinline__ void red4(float* addr, float4 v) {
    asm volatile("red.global.add.v4.f32 [%0], {%1,%2,%3,%4};"
                 :: "l"(addr), "f"(v.x), "f"(v.y), "f"(v.z), "f"(v.w) : "memory");
}
__device__ __forceinline__ void red1(float* addr, float v) {
    asm volatile("red.global.add.f32 [%0], %1;" :: "l"(addr), "f"(v) : "memory");
}

// ---------------------------------------------------------------------------
// Kernel A: xl = x @ Wl1, xr = x @ Wr1  (combined [64,32] weight tile in smem)
// Also zeroes g_agg1 (3125 blocks * 256 threads * 2 floats = exactly N*16).
// ---------------------------------------------------------------------------
__global__ __launch_bounds__(256) void k_proj(const float* __restrict__ x,
                                              const float* __restrict__ Wl1,
                                              const float* __restrict__ Wr1) {
    __shared__ float sW[64][32];
    __shared__ float sx[32][64];
    int tid = threadIdx.x;

    for (int i = tid; i < 64 * 16; i += 256) {
        int k = i >> 4, j = i & 15;
        sW[k][j]      = Wl1[i];
        sW[k][j + 16] = Wr1[i];
    }
    int nodeBase = blockIdx.x * 32;
    const float4* x4 = (const float4*)(x + (size_t)nodeBase * NF);
    #pragma unroll
    for (int i = tid; i < 512; i += 256) {
        float4 v = x4[i];
        int row = i >> 4;
        int c = (i & 15) * 4;
        sx[row][c] = v.x; sx[row][c+1] = v.y; sx[row][c+2] = v.z; sx[row][c+3] = v.w;
    }
    __syncthreads();

    int j  = tid & 31;
    int nl = tid >> 5;
    float a0 = 0.f, a1 = 0.f, a2 = 0.f, a3 = 0.f;
    #pragma unroll
    for (int k = 0; k < 64; k++) {
        float w = sW[k][j];
        a0 = fmaf(sx[nl     ][k], w, a0);
        a1 = fmaf(sx[nl +  8][k], w, a1);
        a2 = fmaf(sx[nl + 16][k], w, a2);
        a3 = fmaf(sx[nl + 24][k], w, a3);
    }
    float acc[4] = {a0, a1, a2, a3};
    #pragma unroll
    for (int i = 0; i < 4; i++) {
        int node = nodeBase + nl + i * 8;
        if (j < 16) g_xl[node * NH + j]        = acc[i];
        else        g_xr[node * NH + (j - 16)] = acc[i];
    }
    size_t gt = (size_t)blockIdx.x * 256 + tid;
    ((float2*)g_agg1)[gt] = make_float2(0.f, 0.f);
}

// ---------------------------------------------------------------------------
// Kernel B: edge pass 1 — 4 edges/thread, vector loads front-batched for MLP.
// Gather xl[src] (16f), vector-RED into agg1[dst], emit compacted records.
// ---------------------------------------------------------------------------
__global__ __launch_bounds__(256) void k_edge1(const int* __restrict__ ei,
                                               const float* __restrict__ As,
                                               const float* __restrict__ ws) {
    int q = blockIdx.x * 256 + threadIdx.x;   // quad index
    if (q >= E4) return;
    // front-batched independent 16B loads (MLP=4)
    int4   s4 = ((const int4*)ei)[q];
    int4   d4 = ((const int4*)(ei + N_EDGES))[q];
    float4 a0 = ((const float4*)As)[q];
    float4 a1 = ((const float4*)(As + N_EDGES))[q];
    float w0 = ws[0], w1 = ws[1];

    int s[4] = {s4.x, s4.y, s4.z, s4.w};
    int d[4] = {d4.x, d4.y, d4.z, d4.w};
    float ewm[4] = {w0*a0.x + w1*a1.x, w0*a0.y + w1*a1.y,
                    w0*a0.z + w1*a1.z, w0*a0.w + w1*a1.w};
    bool keep[4];
    #pragma unroll
    for (int i = 0; i < 4; i++) {
        keep[i] = (ewm[i] != 0.0f) & ((unsigned)s[i] < N_NODES) & ((unsigned)d[i] < N_NODES);
        if (!keep[i]) d[i] = -1;
    }
    // two 16B record writes
    ((int4*)g_rec)[2*q]     = make_int4(s[0], d[0], s[1], d[1]);
    ((int4*)g_rec)[2*q + 1] = make_int4(s[2], d[2], s[3], d[3]);

    // front-batch all gathers (up to 16 independent 16B loads)
    float4 v[4][4];
    #pragma unroll
    for (int i = 0; i < 4; i++) {
        const float4* xs = (const float4*)g_xl + (size_t)(keep[i] ? s[i] : 0) * 4;
        v[i][0] = xs[0]; v[i][1] = xs[1]; v[i][2] = xs[2]; v[i][3] = xs[3];
    }
    #pragma unroll
    for (int i = 0; i < 4; i++) {
        if (keep[i]) {
            float* base = g_agg1 + (size_t)d[i] * NH;
            red4(base,      v[i][0]);
            red4(base + 4,  v[i][1]);
            red4(base + 8,  v[i][2]);
            red4(base + 12, v[i][3]);
        }
    }
}

// ---------------------------------------------------------------------------
// Kernel C: per-node — h = relu(agg1 + xr + bl1); hl = h.Wl2; hr = h.Wr2;
// out[n] = hr + bl2 (initializes poisoned d_out), g_hl[n] = hl for pass 2.
// ---------------------------------------------------------------------------
__global__ __launch_bounds__(256) void k_node(const float* __restrict__ bl1,
                                              const float* __restrict__ Wl2,
                                              const float* __restrict__ bl2,
                                              const float* __restrict__ Wr2,
                                              float* __restrict__ out) {
    int n = blockIdx.x * 256 + threadIdx.x;
    if (n >= N_NODES) return;
    const float4* a4 = (const float4*)g_agg1 + (size_t)n * 4;
    const float4* r4 = (const float4*)g_xr   + (size_t)n * 4;
    float hl = 0.f, hr = 0.f;
    #pragma unroll
    for (int qq = 0; qq < 4; qq++) {
        float4 a = a4[qq];
        float4 r = r4[qq];
        float h0 = fmaxf(a.x + r.x + bl1[qq * 4 + 0], 0.f);
        float h1 = fmaxf(a.y + r.y + bl1[qq * 4 + 1], 0.f);
        float h2 = fmaxf(a.z + r.z + bl1[qq * 4 + 2], 0.f);
        float h3 = fmaxf(a.w + r.w + bl1[qq * 4 + 3], 0.f);
        hl = fmaf(h0, Wl2[qq * 4 + 0], hl);
        hl = fmaf(h1, Wl2[qq * 4 + 1], hl);
        hl = fmaf(h2, Wl2[qq * 4 + 2], hl);
        hl = fmaf(h3, Wl2[qq * 4 + 3], hl);
        hr = fmaf(h0, Wr2[qq * 4 + 0], hr);
        hr = fmaf(h1, Wr2[qq * 4 + 1], hr);
        hr = fmaf(h2, Wr2[qq * 4 + 2], hr);
        hr = fmaf(h3, Wr2[qq * 4 + 3], hr);
    }
    g_hl[n] = hl;
    out[n] = hr + bl2[0];
}

// ---------------------------------------------------------------------------
// Kernel D: edge pass 2 — 4 edges/thread, scalar RED of hl[src] into out[dst].
// ---------------------------------------------------------------------------
__global__ __launch_bounds__(256) void k_edge2(float* __restrict__ out) {
    int q = blockIdx.x * 256 + threadIdx.x;
    if (q >= E4) return;
    int4 r0 = ((const int4*)g_rec)[2*q];       // s0,d0,s1,d1
    int4 r1 = ((const int4*)g_rec)[2*q + 1];   // s2,d2,s3,d3
    int s[4] = {r0.x, r0.z, r1.x, r1.z};
    int d[4] = {r0.y, r0.w, r1.y, r1.w};
    float h[4];
    #pragma unroll
    for (int i = 0; i < 4; i++)
        h[i] = g_hl[d[i] >= 0 ? s[i] : 0];     // front-batched gathers
    #pragma unroll
    for (int i = 0; i < 4; i++)
        if (d[i] >= 0) red1(out + d[i], h[i]);
}

extern "C" void kernel_launch(void* const* d_in, const int* in_sizes, int n_in,
                              void* d_out, int out_size) {
    const float* x   = (const float*)d_in[0];
    const int*   ei  = (const int*)d_in[1];     // int32 (jax x64 disabled)
    const float* As  = (const float*)d_in[2];
    const float* ws  = (const float*)d_in[3];
    const float* Wl1 = (const float*)d_in[4];
    const float* bl1 = (const float*)d_in[5];
    const float* Wr1 = (const float*)d_in[6];
    const float* Wl2 = (const float*)d_in[7];
    const float* bl2 = (const float*)d_in[8];
    const float* Wr2 = (const float*)d_in[9];
    float* out = (float*)d_out;

    k_proj <<<N_NODES / 32,          256>>>(x, Wl1, Wr1);
    k_edge1<<<(E4 + 255) / 256,      256>>>(ei, As, ws);
    k_node <<<(N_NODES + 255) / 256, 256>>>(bl1, Wl2, bl2, Wr2, out);
    k_edge2<<<(E4 + 255) / 256,      256>>>(out);
}

// round 5
// speedup vs baseline: 1.3218x; 1.3218x over previous
#include <cuda_runtime.h>
#include <cuda_fp16.h>

#define N_NODES 100000
#define N_EDGES 1600000
#define NF 64
#define NH 16
#define E4 (N_EDGES / 4)   // 400000 quad-edge groups

// scratch (no allocs allowed) — 16B-aligned for vector access
__device__ __align__(16) __half2 g_xl[N_NODES * 8];    // x @ Wl1, fp16x2 packed
__device__ __align__(16) __half2 g_agg1[N_NODES * 8];  // segment_sum of xl[src], fp16x2
__device__ __align__(16) float   g_xr[N_NODES * NH];   // x @ Wr1 (fp32)
__device__ __align__(16) float   g_hl[N_NODES];        // h @ Wl2 (scalar per node)
__device__ __align__(16) int2    g_rec[N_EDGES];       // compacted (src, dst-or-neg)

__device__ __forceinline__ void redh8(__half2* addr, int4 v) {
    // 8 fp16 adds in one vector reduction (8 halves = 4 words vs 4 words fp32=4 floats)
    asm volatile("red.global.add.noftz.v4.f16x2 [%0], {%1,%2,%3,%4};"
                 :: "l"(addr), "r"(v.x), "r"(v.y), "r"(v.z), "r"(v.w) : "memory");
}
__device__ __forceinline__ void red1(float* addr, float v) {
    asm volatile("red.global.add.f32 [%0], %1;" :: "l"(addr), "f"(v) : "memory");
}

// ---------------------------------------------------------------------------
// Kernel A: xl = fp16(x @ Wl1), xr = x @ Wr1. Also zeroes g_agg1
// (3125 blocks * 256 threads * 1 u32 = exactly 800000 = N*8 half2 words).
// ---------------------------------------------------------------------------
__global__ __launch_bounds__(256) void k_proj(const float* __restrict__ x,
                                              const float* __restrict__ Wl1,
                                              const float* __restrict__ Wr1) {
    __shared__ float sW[64][32];
    __shared__ float sx[32][64];
    int tid = threadIdx.x;

    for (int i = tid; i < 64 * 16; i += 256) {
        int k = i >> 4, j = i & 15;
        sW[k][j]      = Wl1[i];
        sW[k][j + 16] = Wr1[i];
    }
    int nodeBase = blockIdx.x * 32;
    const float4* x4 = (const float4*)(x + (size_t)nodeBase * NF);
    #pragma unroll
    for (int i = tid; i < 512; i += 256) {
        float4 v = x4[i];
        int row = i >> 4;
        int c = (i & 15) * 4;
        sx[row][c] = v.x; sx[row][c+1] = v.y; sx[row][c+2] = v.z; sx[row][c+3] = v.w;
    }
    __syncthreads();

    int j  = tid & 31;   // 0..15: xl channel j; 16..31: xr channel j-16
    int nl = tid >> 5;
    float a0 = 0.f, a1 = 0.f, a2 = 0.f, a3 = 0.f;
    #pragma unroll
    for (int k = 0; k < 64; k++) {
        float w = sW[k][j];
        a0 = fmaf(sx[nl     ][k], w, a0);
        a1 = fmaf(sx[nl +  8][k], w, a1);
        a2 = fmaf(sx[nl + 16][k], w, a2);
        a3 = fmaf(sx[nl + 24][k], w, a3);
    }
    float acc[4] = {a0, a1, a2, a3};
    #pragma unroll
    for (int i = 0; i < 4; i++) {
        int node = nodeBase + nl + i * 8;
        float other = __shfl_xor_sync(0xffffffffu, acc[i], 1);
        if (j < 16) {
            if ((j & 1) == 0)   // even lane packs (ch j, ch j+1)
                g_xl[node * 8 + (j >> 1)] = __floats2half2_rn(acc[i], other);
        } else {
            g_xr[node * NH + (j - 16)] = acc[i];
        }
    }
    unsigned gt = blockIdx.x * 256 + tid;        // 0..799999
    ((unsigned*)g_agg1)[gt] = 0u;
}

// ---------------------------------------------------------------------------
// Kernel B: edge pass 1 — 4 edges/thread. Gather xl[src] (32B fp16), two
// v4.f16x2 vector-REDs into agg1[dst] (8 atomic words/edge vs 16 for fp32).
// ---------------------------------------------------------------------------
__global__ __launch_bounds__(256) void k_edge1(const int* __restrict__ ei,
                                               const float* __restrict__ As,
                                               const float* __restrict__ ws) {
    int q = blockIdx.x * 256 + threadIdx.x;
    if (q >= E4) return;
    int4   s4 = ((const int4*)ei)[q];
    int4   d4 = ((const int4*)(ei + N_EDGES))[q];
    float4 a0 = ((const float4*)As)[q];
    float4 a1 = ((const float4*)(As + N_EDGES))[q];
    float w0 = ws[0], w1 = ws[1];

    int s[4] = {s4.x, s4.y, s4.z, s4.w};
    int d[4] = {d4.x, d4.y, d4.z, d4.w};
    float ewm[4] = {w0*a0.x + w1*a1.x, w0*a0.y + w1*a1.y,
                    w0*a0.z + w1*a1.z, w0*a0.w + w1*a1.w};
    bool keep[4];
    #pragma unroll
    for (int i = 0; i < 4; i++) {
        keep[i] = (ewm[i] != 0.0f) & ((unsigned)s[i] < N_NODES) & ((unsigned)d[i] < N_NODES);
        if (!keep[i]) d[i] = -1;
    }
    ((int4*)g_rec)[2*q]     = make_int4(s[0], d[0], s[1], d[1]);
    ((int4*)g_rec)[2*q + 1] = make_int4(s[2], d[2], s[3], d[3]);

    int4 v[4][2];
    #pragma unroll
    for (int i = 0; i < 4; i++) {
        const int4* xs = (const int4*)g_xl + (size_t)(keep[i] ? s[i] : 0) * 2;
        v[i][0] = xs[0]; v[i][1] = xs[1];
    }
    #pragma unroll
    for (int i = 0; i < 4; i++) {
        if (keep[i]) {
            __half2* base = g_agg1 + (size_t)d[i] * 8;
            redh8(base,     v[i][0]);
            redh8(base + 4, v[i][1]);
        }
    }
}

// ---------------------------------------------------------------------------
// Kernel C: per-node — h = relu(agg1 + xr + bl1); hl = h.Wl2; hr = h.Wr2;
// out[n] = hr + bl2 (initializes poisoned d_out), g_hl[n] = hl for pass 2.
// ---------------------------------------------------------------------------
__global__ __launch_bounds__(256) void k_node(const float* __restrict__ bl1,
                                              const float* __restrict__ Wl2,
                                              const float* __restrict__ bl2,
                                              const float* __restrict__ Wr2,
                                              float* __restrict__ out) {
    int n = blockIdx.x * 256 + threadIdx.x;
    if (n >= N_NODES) return;
    int4 A0 = ((const int4*)g_agg1)[n * 2];
    int4 A1 = ((const int4*)g_agg1)[n * 2 + 1];
    __half2 ah[8];
    *(int4*)(ah)     = A0;
    *(int4*)(ah + 4) = A1;
    const float4* r4 = (const float4*)g_xr + (size_t)n * 4;
    float hl = 0.f, hr = 0.f;
    #pragma unroll
    for (int qq = 0; qq < 4; qq++) {
        float4 r = r4[qq];
        float2 p0 = __half22float2(ah[qq * 2]);
        float2 p1 = __half22float2(ah[qq * 2 + 1]);
        float h0 = fmaxf(p0.x + r.x + bl1[qq * 4 + 0], 0.f);
        float h1 = fmaxf(p0.y + r.y + bl1[qq * 4 + 1], 0.f);
        float h2 = fmaxf(p1.x + r.z + bl1[qq * 4 + 2], 0.f);
        float h3 = fmaxf(p1.y + r.w + bl1[qq * 4 + 3], 0.f);
        hl = fmaf(h0, Wl2[qq * 4 + 0], hl);
        hl = fmaf(h1, Wl2[qq * 4 + 1], hl);
        hl = fmaf(h2, Wl2[qq * 4 + 2], hl);
        hl = fmaf(h3, Wl2[qq * 4 + 3], hl);
        hr = fmaf(h0, Wr2[qq * 4 + 0], hr);
        hr = fmaf(h1, Wr2[qq * 4 + 1], hr);
        hr = fmaf(h2, Wr2[qq * 4 + 2], hr);
        hr = fmaf(h3, Wr2[qq * 4 + 3], hr);
    }
    g_hl[n] = hl;
    out[n] = hr + bl2[0];
}

// ---------------------------------------------------------------------------
// Kernel D: edge pass 2 — 4 edges/thread, scalar RED of hl[src] into out[dst].
// ---------------------------------------------------------------------------
__global__ __launch_bounds__(256) void k_edge2(float* __restrict__ out) {
    int q = blockIdx.x * 256 + threadIdx.x;
    if (q >= E4) return;
    int4 r0 = ((const int4*)g_rec)[2*q];       // s0,d0,s1,d1
    int4 r1 = ((const int4*)g_rec)[2*q + 1];   // s2,d2,s3,d3
    int s[4] = {r0.x, r0.z, r1.x, r1.z};
    int d[4] = {r0.y, r0.w, r1.y, r1.w};
    float h[4];
    #pragma unroll
    for (int i = 0; i < 4; i++)
        h[i] = g_hl[d[i] >= 0 ? s[i] : 0];
    #pragma unroll
    for (int i = 0; i < 4; i++)
        if (d[i] >= 0) red1(out + d[i], h[i]);
}

extern "C" void kernel_launch(void* const* d_in, const int* in_sizes, int n_in,
                              void* d_out, int out_size) {
    const float* x   = (const float*)d_in[0];
    const int*   ei  = (const int*)d_in[1];     // int32 (jax x64 disabled)
    const float* As  = (const float*)d_in[2];
    const float* ws  = (const float*)d_in[3];
    const float* Wl1 = (const float*)d_in[4];
    const float* bl1 = (const float*)d_in[5];
    const float* Wr1 = (const float*)d_in[6];
    const float* Wl2 = (const float*)d_in[7];
    const float* bl2 = (const float*)d_in[8];
    const float* Wr2 = (const float*)d_in[9];
    float* out = (float*)d_out;

    k_proj <<<N_NODES / 32,          256>>>(x, Wl1, Wr1);
    k_edge1<<<(E4 + 255) / 256,      256>>>(ei, As, ws);
    k_node <<<(N_NODES + 255) / 256, 256>>>(bl1, Wl2, bl2, Wr2, out);
    k_edge2<<<(E4 + 255) / 256,      256>>>(out);
}